// round 17
// baseline (speedup 1.0000x reference)
#include <cuda_runtime.h>
#include <cuda_fp16.h>
#include <cstdint>

#define NN     50000
#define EE     800000
#define EI     200000
#define SLOPE  0.2f

// ---- scratch layout inside d_out (float offsets) -------------------------------
#define S_FT    6400000u     // NN*128 floats (fp32 ft)
#define S_H1   12800000u     // 6.4M floats : layer-1 output (fp32)
#define S_EL   19200000u
#define S_ER   19400000u
#define S_OFF  19600000u     // NN+1 ints : CSR row offsets
#define S_CUR  19800000u     // NN   ints : counts -> cursors
#define S_EIDX 20000000u     // EE   ints : src id per CSR slot
#define S_DST  20800000u     // EE   ints : dst id per CSR slot
#define S_A    21600000u     // EE*4 floats : attention per slot (ends 24.8M)

__device__ __forceinline__ uint32_t smem_u32(const void* p) {
    uint32_t a;
    asm("{ .reg .u64 t; cvta.to.shared.u64 t, %1; cvt.u32.u64 %0, t; }"
        : "=r"(a) : "l"(p));
    return a;
}

#define LDSM_X4(r0, r1, r2, r3, addr)                                        \
    asm volatile("ldmatrix.sync.aligned.m8n8.x4.shared.b16 {%0,%1,%2,%3},[%4];" \
                 : "=r"(r0), "=r"(r1), "=r"(r2), "=r"(r3) : "r"(addr))

#define LDSM_X4_T(r0, r1, r2, r3, addr)                                      \
    asm volatile("ldmatrix.sync.aligned.m8n8.x4.trans.shared.b16 {%0,%1,%2,%3},[%4];" \
                 : "=r"(r0), "=r"(r1), "=r"(r2), "=r"(r3) : "r"(addr))

#define MMA16816(c0, c1, c2, c3, a0, a1, a2, a3, b0, b1)                     \
    asm volatile("mma.sync.aligned.m16n8k16.row.col.f32.f16.f16.f32 "        \
                 "{%0,%1,%2,%3},{%4,%5,%6,%7},{%8,%9},{%0,%1,%2,%3};"        \
                 : "+f"(c0), "+f"(c1), "+f"(c2), "+f"(c3)                    \
                 : "r"(a0), "r"(a1), "r"(a2), "r"(a3), "r"(b0), "r"(b1))

// =================================================================================
// Tensor-core GEMM: ft = X @ W (fp16 in, fp32 acc), fused per-head el/er,
// FP32 ft out (aggregate is issue-bound, not BW-bound — fp32 kills the converts).
// 256 threads = 8 warps; CTA tile 128x128; warp tile m16 x n128; K=128 in 8 chunks.
// gemm1 also does the CSR histogram (keeps agg1 in ncu's capture slot = launch #4).
// =================================================================================
#define XPH 136                               // padded halves per row (272B stride)
#define FPAD 132                              // fp32 staging row stride (floats)
__global__ void __launch_bounds__(256, 2)
gat_gemm_tc(const float* __restrict__ X, const float* __restrict__ W,
            const float* __restrict__ al, const float* __restrict__ ar,
            float* __restrict__ ftf, float* __restrict__ el,
            float* __restrict__ er,
            const int* __restrict__ histdst, int* __restrict__ cnt)
{
    extern __shared__ __half sm[];
    __half* Xh = sm;                          // [128][XPH]
    __half* Wh = sm + 128 * XPH;              // [128][XPH]
    float*  als = (float*)(sm + 2 * 128 * XPH);        // [128]
    float*  ars = als + 128;                           // [128]

    const int t    = threadIdx.x;
    const int lane = t & 31;
    const int warp = t >> 5;                  // 0..7
    const int rw   = warp * 16;
    const int row0 = blockIdx.x * 128;

    // fused histogram (layer-1 call only)
    if (histdst != nullptr) {
        int gtid = blockIdx.x * 256 + t;      // grid*256 = 100096
        #pragma unroll
        for (int i = 0; i < 8; i++) {
            int e = gtid + i * 100096;
            if (e < EE) atomicAdd(&cnt[histdst[e]], 1);
        }
    }

    if (t < 128) { als[t] = al[t]; ars[t] = ar[t]; }

    // load W -> fp16 smem
    {
        const float4* W4 = reinterpret_cast<const float4*>(W);
        for (int i = t; i < 128 * 32; i += 256) {
            float4 v = W4[i];
            int r = i >> 5, c = (i & 31) * 4;
            __half2 p0 = __floats2half2_rn(v.x, v.y);
            __half2 p1 = __floats2half2_rn(v.z, v.w);
            *reinterpret_cast<__half2*>(&Wh[r * XPH + c])     = p0;
            *reinterpret_cast<__half2*>(&Wh[r * XPH + c + 2]) = p1;
        }
    }
    // load X tile -> fp16 smem (zero-pad rows >= NN)
    {
        const float4* X4 = reinterpret_cast<const float4*>(X);
        for (int i = t; i < 128 * 32; i += 256) {
            int r = i >> 5, c = (i & 31) * 4;
            int row = row0 + r;
            float4 v = (row < NN) ? X4[(size_t)row * 32 + (i & 31)]
                                  : make_float4(0.f, 0.f, 0.f, 0.f);
            __half2 p0 = __floats2half2_rn(v.x, v.y);
            __half2 p1 = __floats2half2_rn(v.z, v.w);
            *reinterpret_cast<__half2*>(&Xh[r * XPH + c])     = p0;
            *reinterpret_cast<__half2*>(&Xh[r * XPH + c + 2]) = p1;
        }
    }
    __syncthreads();

    // acc[j][0..3]: n-tile j (cols 8j..8j+7); rows (rw+lane/4, +8),
    // cols 8j+2*(lane&3)+{0,1}
    float acc[16][4];
    #pragma unroll
    for (int j = 0; j < 16; j++)
        #pragma unroll
        for (int c = 0; c < 4; c++) acc[j][c] = 0.f;

    const uint32_t aBase = smem_u32(Xh) +
        (((rw + (lane & 15)) * XPH) + (lane >> 4) * 8) * 2;
    const uint32_t bBase = smem_u32(Wh) +
        (((lane & 15) * XPH) + (lane >> 4) * 8) * 2;

    #pragma unroll 2
    for (int kb = 0; kb < 8; kb++) {
        uint32_t a0, a1, a2, a3;
        LDSM_X4(a0, a1, a2, a3, aBase + kb * 16 * 2);
        #pragma unroll
        for (int j2 = 0; j2 < 8; j2++) {
            uint32_t b0, b1, b2, b3;
            LDSM_X4_T(b0, b1, b2, b3, bBase + (kb * 16 * XPH + j2 * 16) * 2);
            MMA16816(acc[2*j2][0],   acc[2*j2][1],   acc[2*j2][2],   acc[2*j2][3],
                     a0, a1, a2, a3, b0, b1);
            MMA16816(acc[2*j2+1][0], acc[2*j2+1][1], acc[2*j2+1][2], acc[2*j2+1][3],
                     a0, a1, a2, a3, b2, b3);
        }
    }

    // ---- el/er: per-head dot (head h = tiles 4h..4h+3), reduce over 4 lanes ----
    const int q = lane & 3;
    float pe0[4], pr0[4], pe1[4], pr1[4];
    #pragma unroll
    for (int h = 0; h < 4; h++) { pe0[h]=pr0[h]=pe1[h]=pr1[h]=0.f; }
    #pragma unroll
    for (int j = 0; j < 16; j++) {
        int c = 8 * j + 2 * q, h = j >> 2;
        float a0l = als[c], a1l = als[c + 1];
        float a0r = ars[c], a1r = ars[c + 1];
        pe0[h] += acc[j][0] * a0l + acc[j][1] * a1l;
        pr0[h] += acc[j][0] * a0r + acc[j][1] * a1r;
        pe1[h] += acc[j][2] * a0l + acc[j][3] * a1l;
        pr1[h] += acc[j][2] * a0r + acc[j][3] * a1r;
    }
    #pragma unroll
    for (int h = 0; h < 4; h++) {
        pe0[h] += __shfl_xor_sync(0xffffffffu, pe0[h], 1);
        pe0[h] += __shfl_xor_sync(0xffffffffu, pe0[h], 2);
        pr0[h] += __shfl_xor_sync(0xffffffffu, pr0[h], 1);
        pr0[h] += __shfl_xor_sync(0xffffffffu, pr0[h], 2);
        pe1[h] += __shfl_xor_sync(0xffffffffu, pe1[h], 1);
        pe1[h] += __shfl_xor_sync(0xffffffffu, pe1[h], 2);
        pr1[h] += __shfl_xor_sync(0xffffffffu, pr1[h], 1);
        pr1[h] += __shfl_xor_sync(0xffffffffu, pr1[h], 2);
    }
    int r0g = row0 + rw + (lane >> 2);
    int r1g = r0g + 8;
    if (q == 0) {
        if (r0g < NN) {
            *reinterpret_cast<float4*>(&el[(size_t)r0g * 4]) =
                make_float4(pe0[0], pe0[1], pe0[2], pe0[3]);
            *reinterpret_cast<float4*>(&er[(size_t)r0g * 4]) =
                make_float4(pr0[0], pr0[1], pr0[2], pr0[3]);
        }
        if (r1g < NN) {
            *reinterpret_cast<float4*>(&el[(size_t)r1g * 4]) =
                make_float4(pe1[0], pe1[1], pe1[2], pe1[3]);
            *reinterpret_cast<float4*>(&er[(size_t)r1g * 4]) =
                make_float4(pr1[0], pr1[1], pr1[2], pr1[3]);
        }
    }

    // ---- ft: stage FP32 in smem (reuse Xh+Wh region: 128*132*4 = 67.6KB), then
    //      coalesced float4 store ----
    __syncthreads();
    float* fs = (float*)sm;                   // [128][FPAD]
    {
        int rs0 = rw + (lane >> 2);
        #pragma unroll
        for (int j = 0; j < 16; j++) {
            int c = 8 * j + 2 * q;
            fs[rs0 * FPAD + c]           = acc[j][0];
            fs[rs0 * FPAD + c + 1]       = acc[j][1];
            fs[(rs0 + 8) * FPAD + c]     = acc[j][2];
            fs[(rs0 + 8) * FPAD + c + 1] = acc[j][3];
        }
    }
    __syncthreads();
    for (int i = t; i < 128 * 32; i += 256) {
        int r = i >> 5, seg = i & 31;
        int row = row0 + r;
        if (row < NN) {
            float4 v = *reinterpret_cast<const float4*>(&fs[r * FPAD + seg * 4]);
            *reinterpret_cast<float4*>(&ftf[(size_t)row * 128 + seg * 4]) = v;
        }
    }
}

// =================================================================================
// CSR scan (single block) — counts -> offsets + cursors
// =================================================================================
__global__ void __launch_bounds__(1024, 1)
scan_kernel(int* __restrict__ cntcur, int* __restrict__ off)
{
    __shared__ int ssum[1024];
    const int t = threadIdx.x;
    const int C = (NN + 1023) / 1024;
    int lo = t * C, hi = min(lo + C, NN);
    int s = 0;
    for (int i = lo; i < hi; i++) s += cntcur[i];
    ssum[t] = s;
    __syncthreads();
    for (int d = 1; d < 1024; d <<= 1) {
        int v = (t >= d) ? ssum[t - d] : 0;
        __syncthreads();
        ssum[t] += v;
        __syncthreads();
    }
    int run = (t > 0) ? ssum[t - 1] : 0;
    for (int i = lo; i < hi; i++) {
        int c = cntcur[i];
        off[i] = run;
        cntcur[i] = run;
        run += c;
    }
    if (t == 1023) off[NN] = ssum[1023];
}

// scatter + layer-1 attention fused
__global__ void scatter_att_kernel(const int* __restrict__ src, const int* __restrict__ dst,
                                   int* __restrict__ cur, int* __restrict__ eidx,
                                   int* __restrict__ dslot,
                                   const float* __restrict__ el,
                                   const float* __restrict__ er,
                                   float4* __restrict__ a4)
{
    int e = blockIdx.x * blockDim.x + threadIdx.x;
    if (e >= EE) return;
    int s = src[e], d = dst[e];
    int pos = atomicAdd(&cur[d], 1);
    eidx[pos]  = s;
    dslot[pos] = d;
    float4 l = *reinterpret_cast<const float4*>(&el[(size_t)s * 4]);
    float4 r = *reinterpret_cast<const float4*>(&er[(size_t)d * 4]);
    float4 v;
    float vx = l.x + r.x; vx = (vx > 0.f) ? vx : SLOPE * vx; v.x = __expf(vx);
    float vy = l.y + r.y; vy = (vy > 0.f) ? vy : SLOPE * vy; v.y = __expf(vy);
    float vz = l.z + r.z; vz = (vz > 0.f) ? vz : SLOPE * vz; v.z = __expf(vz);
    float vw = l.w + r.w; vw = (vw > 0.f) ? vw : SLOPE * vw; v.w = __expf(vw);
    a4[pos] = v;
}

// layer-2 attention (CSR already built)
__global__ void att_kernel(const int* __restrict__ eidx, const int* __restrict__ dslot,
                           const float* __restrict__ el, const float* __restrict__ er,
                           float4* __restrict__ a4)
{
    int t = blockIdx.x * blockDim.x + threadIdx.x;
    if (t >= EE) return;
    int s = eidx[t], d = dslot[t];
    float4 l = *reinterpret_cast<const float4*>(&el[(size_t)s * 4]);
    float4 r = *reinterpret_cast<const float4*>(&er[(size_t)d * 4]);
    float4 v;
    float vx = l.x + r.x; vx = (vx > 0.f) ? vx : SLOPE * vx; v.x = __expf(vx);
    float vy = l.y + r.y; vy = (vy > 0.f) ? vy : SLOPE * vy; v.y = __expf(vy);
    float vz = l.z + r.z; vz = (vz > 0.f) ? vz : SLOPE * vz; v.z = __expf(vz);
    float vw = l.w + r.w; vw = (vw > 0.f) ? vw : SLOPE * vw; v.w = __expf(vw);
    a4[t] = v;
}

// =================================================================================
// Gather aggregation + fused normalize + ELU. One warp per dst node, fp32 ft rows.
// NO shuffles, NO den reduction: lane loads its own head's attention directly
// (afl[(p+e)*4 + hsel]); all 8 lanes of a head group compute identical den.
// =================================================================================
__device__ __forceinline__ float elu1(float x) { return (x > 0.f) ? x : expm1f(x); }

__global__ void __launch_bounds__(256, 5)
gat_aggregate_kernel(const int* __restrict__ off, const int* __restrict__ eidx,
                     const float* __restrict__ afl, const float* __restrict__ ftf,
                     float* __restrict__ out)
{
    int d = (blockIdx.x * blockDim.x + threadIdx.x) >> 5;
    if (d >= NN) return;
    const int lane = threadIdx.x & 31;
    const int hsel = lane >> 3;            // head of this lane's 4-col chunk

    int p0 = off[d], p1 = off[d + 1];
    float4 acc = make_float4(0.f, 0.f, 0.f, 0.f);
    float den = 0.f;
    const float4* ft4 = reinterpret_cast<const float4*>(ftf);

    int p = p0;
    int pre = min(p1, (p0 + 3) & ~3);
    for (; p < pre; ++p) {
        int s = __ldg(&eidx[p]);
        float a = __ldg(&afl[(size_t)p * 4 + hsel]);
        float4 f = ft4[(size_t)s * 32 + lane];
        den += a;
        acc.x += a * f.x; acc.y += a * f.y;
        acc.z += a * f.z; acc.w += a * f.w;
    }
    if (p + 4 <= p1) {
        int4 s4 = __ldg(reinterpret_cast<const int4*>(&eidx[p]));
        for (; p + 4 <= p1; p += 4) {
            int4 nxt = (p + 8 <= p1)
                     ? __ldg(reinterpret_cast<const int4*>(&eidx[p + 4])) : s4;
            float a0 = __ldg(&afl[(size_t)p * 4 + hsel]);
            float a1 = __ldg(&afl[(size_t)p * 4 + 4 + hsel]);
            float a2 = __ldg(&afl[(size_t)p * 4 + 8 + hsel]);
            float a3 = __ldg(&afl[(size_t)p * 4 + 12 + hsel]);
            float4 f0 = ft4[(size_t)s4.x * 32 + lane];
            float4 f1 = ft4[(size_t)s4.y * 32 + lane];
            float4 f2 = ft4[(size_t)s4.z * 32 + lane];
            float4 f3 = ft4[(size_t)s4.w * 32 + lane];
            den += (a0 + a1) + (a2 + a3);
            acc.x += a0 * f0.x + a1 * f1.x + a2 * f2.x + a3 * f3.x;
            acc.y += a0 * f0.y + a1 * f1.y + a2 * f2.y + a3 * f3.y;
            acc.z += a0 * f0.z + a1 * f1.z + a2 * f2.z + a3 * f3.z;
            acc.w += a0 * f0.w + a1 * f1.w + a2 * f2.w + a3 * f3.w;
            s4 = nxt;
        }
    }
    for (; p < p1; ++p) {
        int s = __ldg(&eidx[p]);
        float a = __ldg(&afl[(size_t)p * 4 + hsel]);
        float4 f = ft4[(size_t)s * 32 + lane];
        den += a;
        acc.x += a * f.x; acc.y += a * f.y;
        acc.z += a * f.z; acc.w += a * f.w;
    }

    float inv = 1.0f / fmaxf(den, 1e-9f);
    float4 r;
    r.x = elu1(acc.x * inv);
    r.y = elu1(acc.y * inv);
    r.z = elu1(acc.z * inv);
    r.w = elu1(acc.w * inv);
    reinterpret_cast<float4*>(out)[(size_t)d * 32 + lane] = r;
}

// =================================================================================
// Edge features, 2 float4 per thread.
// =================================================================================
__global__ void __launch_bounds__(256)
gat_edgefeat_kernel(const float* __restrict__ hf,
                    const int* __restrict__ ind0,
                    const int* __restrict__ ind1,
                    float* __restrict__ out)
{
    int idx = blockIdx.x * blockDim.x + threadIdx.x;
    if (idx >= EI * 32) return;
    int p  = idx >> 5;
    int tq = idx & 31;
    int i0 = __ldg(&ind0[p]);
    int i1 = __ldg(&ind1[p]);
    const float4* hf4 = reinterpret_cast<const float4*>(hf);
    float4* o4 = reinterpret_cast<float4*>(out) + (size_t)p * 64;
    #pragma unroll
    for (int j = 0; j < 2; j++) {
        int q = tq * 2 + j;
        int h = q >> 4, w = q & 15;
        int node = (w < 8) ? i0 : i1;
        o4[q] = hf4[(size_t)node * 32 + h * 8 + (w & 7)];
    }
}

// =================================================================================
// Launch.  k1 gemm1(+hist), k2 scan, k3 scatter+att1, k4 agg1 (ncu capture slot).
// =================================================================================
extern "C" void kernel_launch(void* const* d_in, const int* in_sizes, int n_in,
                              void* d_out, int out_size)
{
    const float* x      = (const float*)d_in[0];
    const int*   src    = (const int*)  d_in[1];
    const int*   dst    = (const int*)  d_in[2];
    const int*   indics = (const int*)  d_in[3];
    const float* W0     = (const float*)d_in[4];
    const float* al0    = (const float*)d_in[5];
    const float* ar0    = (const float*)d_in[6];
    const float* W1     = (const float*)d_in[7];
    const float* al1    = (const float*)d_in[8];
    const float* ar1    = (const float*)d_in[9];

    float* o     = (float*)d_out;
    float* h_out = o;
    float* edges = o + (size_t)NN * 128;

    float* ftf  = o + S_FT;
    float* h1   = o + S_H1;
    float* el   = o + S_EL;
    float* er   = o + S_ER;
    int*   off  = (int*)(o + S_OFF);
    int*   cur  = (int*)(o + S_CUR);
    int*   eid  = (int*)(o + S_EIDX);
    int*   dsl  = (int*)(o + S_DST);
    float* afl  = o + S_A;
    float4* a4  = (float4*)afl;

    const int gemm_smem = 2 * 128 * XPH * 2 + 2 * 128 * 4;   // 70,656 B
    static int attr_done = 0;
    if (!attr_done) {
        cudaFuncSetAttribute(gat_gemm_tc,
                             cudaFuncAttributeMaxDynamicSharedMemorySize, gemm_smem);
        attr_done = 1;
    }

    const int gemm_grid = (NN + 127) / 128;            // 391
    const int edge_grid = (EE + 255) / 256;
    const int agg_grid  = (NN * 32 + 255) / 256;
    const int ef_grid   = (EI * 32 + 255) / 256;

    cudaMemsetAsync(cur, 0, NN * sizeof(int));         // memset node (not a kernel)

    gat_gemm_tc<<<gemm_grid, 256, gemm_smem>>>(x, W0, al0, ar0, ftf, el, er, dst, cur);
    scan_kernel<<<1, 1024>>>(cur, off);
    scatter_att_kernel<<<edge_grid, 256>>>(src, dst, cur, eid, dsl, el, er, a4);
    gat_aggregate_kernel<<<agg_grid, 256>>>(off, eid, afl, ftf, h1);   // k4 = ncu

    gat_gemm_tc<<<gemm_grid, 256, gemm_smem>>>(h1, W1, al1, ar1, ftf, el, er,
                                               nullptr, nullptr);
    att_kernel<<<edge_grid, 256>>>(eid, dsl, el, er, a4);
    gat_aggregate_kernel<<<agg_grid, 256>>>(off, eid, afl, ftf, h_out);

    gat_edgefeat_kernel<<<ef_grid, 256>>>(h_out, indics, indics + EI, edges);
}